// round 3
// baseline (speedup 1.0000x reference)
#include <cuda_runtime.h>
#include <cstdint>

#define N_NODES 50000
#define N_EDGES 1600000
#define N_FEAT  256
#define N_HID   128
#define N_CLASS 64

#define SCAN_B 1024
#define NBLK_SCAN ((N_NODES + SCAN_B - 1) / SCAN_B)   // 49

// ---------------- device scratch (static, no allocations) ----------------
__device__ float g_deg[N_NODES];
__device__ float g_dinv[N_NODES];
__device__ int   g_cnt[N_NODES];
__device__ int   g_scan_tmp[N_NODES];
__device__ int   g_partials[64];
__device__ int   g_rowptr[N_NODES + 1];
__device__ int   g_cursor[N_NODES];
__device__ int   g_csr_src[N_EDGES];
__device__ float g_csr_w[N_EDGES];
// float4-typed for guaranteed 16B alignment of vector accesses
__device__ float4 g_xw4[(size_t)N_NODES * (N_HID / 4)];    // x @ W1     [N,128]
__device__ float4 g_h4 [(size_t)N_NODES * (N_HID / 4)];    // sigmoid(.) [N,128]
__device__ float4 g_hw4[(size_t)N_NODES * (N_CLASS / 4)];  // h @ W2     [N,64]

// ---------------- prep kernels ----------------
__global__ void k_init() {
    int i = blockIdx.x * blockDim.x + threadIdx.x;
    if (i < N_NODES) { g_deg[i] = 1.0f; g_cnt[i] = 0; }   // self-loop weight 1
}

__global__ void k_deg(const int* __restrict__ ei, const float* __restrict__ ew) {
    int e = blockIdx.x * blockDim.x + threadIdx.x;
    if (e < N_EDGES) {
        int c = ei[N_EDGES + e];
        if ((unsigned)c < N_NODES) {
            atomicAdd(&g_deg[c], ew[e]);
            atomicAdd(&g_cnt[c], 1);
        }
    }
}

__global__ void k_dinv() {
    int i = blockIdx.x * blockDim.x + threadIdx.x;
    if (i < N_NODES) {
        float d = g_deg[i];
        g_dinv[i] = (d > 0.f) ? rsqrtf(d) : 0.f;
    }
}

__global__ void k_scan1() {
    __shared__ int s[SCAN_B];
    int i = blockIdx.x * SCAN_B + threadIdx.x;
    int v = (i < N_NODES) ? g_cnt[i] : 0;
    s[threadIdx.x] = v;
    __syncthreads();
    for (int off = 1; off < SCAN_B; off <<= 1) {
        int t = (threadIdx.x >= off) ? s[threadIdx.x - off] : 0;
        __syncthreads();
        s[threadIdx.x] += t;
        __syncthreads();
    }
    if (i < N_NODES) g_scan_tmp[i] = s[threadIdx.x];      // inclusive
    if (threadIdx.x == SCAN_B - 1) g_partials[blockIdx.x] = s[SCAN_B - 1];
}

__global__ void k_scan2() {
    __shared__ int s[64];
    int t = threadIdx.x;
    int v = (t < NBLK_SCAN) ? g_partials[t] : 0;
    s[t] = v;
    __syncthreads();
    for (int off = 1; off < 64; off <<= 1) {
        int u = (t >= off) ? s[t - off] : 0;
        __syncthreads();
        s[t] += u;
        __syncthreads();
    }
    if (t < NBLK_SCAN) g_partials[t] = s[t] - v;          // exclusive
}

__global__ void k_scan3() {
    int i = blockIdx.x * SCAN_B + threadIdx.x;
    if (i < N_NODES) {
        int ex = g_scan_tmp[i] - g_cnt[i] + g_partials[blockIdx.x];
        g_rowptr[i] = ex;
        g_cursor[i] = ex;
    }
    if (i == 0) g_rowptr[N_NODES] = N_EDGES;
}

__global__ void k_scatter(const int* __restrict__ ei, const float* __restrict__ ew) {
    int e = blockIdx.x * blockDim.x + threadIdx.x;
    if (e < N_EDGES) {
        int r = ei[e];
        int c = ei[N_EDGES + e];
        if ((unsigned)r < N_NODES && (unsigned)c < N_NODES) {
            float nrm = g_dinv[r] * ew[e] * g_dinv[c];
            int p = atomicAdd(&g_cursor[c], 1);
            g_csr_src[p] = r;
            g_csr_w[p]   = nrm;
        }
    }
}

// ---------------- fp32 register-tiled GEMM ----------------
// LAYER 0: C = x(param) @ W1 -> g_xw4   (K=256, NO=128)
// LAYER 1: C = g_h @ W2      -> g_hw4   (K=128, NO=64)
template<int K, int NO, int LAYER>
__global__ __launch_bounds__(256) void k_gemm(const float* __restrict__ Ain,
                                              const float* __restrict__ B, int M) {
    const float* __restrict__ A = (LAYER == 0) ? Ain : (const float*)g_h4;
    float* __restrict__ C = (LAYER == 0) ? (float*)g_xw4 : (float*)g_hw4;

    constexpr int BM = 64, BK = 32;
    constexpr int TN = NO / 16;          // cols per thread: 8 (NO=128) or 4 (NO=64)
    __shared__ float As[BK][BM];         // A tile, transposed
    __shared__ float Bs[BK][NO];
    const int tid = threadIdx.x;
    const int bm  = blockIdx.x * BM;
    const int tx  = tid & 15;            // 16 col groups
    const int ty  = tid >> 4;            // 16 row groups of 4 rows

    float acc[4][TN];
    #pragma unroll
    for (int i = 0; i < 4; i++)
        #pragma unroll
        for (int j = 0; j < TN; j++) acc[i][j] = 0.f;

    for (int k0 = 0; k0 < K; k0 += BK) {
        // A tile: 64x32 floats = 512 float4, 2 per thread
        #pragma unroll
        for (int i = 0; i < 2; i++) {
            int t  = tid * 2 + i;
            int r  = t >> 3;
            int c4 = (t & 7) << 2;
            float4 v = make_float4(0.f, 0.f, 0.f, 0.f);
            if (bm + r < M)
                v = *(const float4*)(A + (size_t)(bm + r) * K + k0 + c4);
            As[c4 + 0][r] = v.x; As[c4 + 1][r] = v.y;
            As[c4 + 2][r] = v.z; As[c4 + 3][r] = v.w;
        }
        // B tile: 32xNO floats
        #pragma unroll
        for (int i = 0; i < NO / 32; i++) {
            int t  = tid * (NO / 32) + i;
            int r  = t / (NO / 4);
            int c4 = (t % (NO / 4)) << 2;
            *(float4*)&Bs[r][c4] = *(const float4*)(B + (size_t)(k0 + r) * NO + c4);
        }
        __syncthreads();

        #pragma unroll
        for (int k = 0; k < BK; k++) {
            float4 a4 = *(const float4*)&As[k][ty * 4];
            float a[4] = {a4.x, a4.y, a4.z, a4.w};
            float b[TN];
            #pragma unroll
            for (int j = 0; j < TN; j += 4) {
                float4 b4 = *(const float4*)&Bs[k][tx * TN + j];
                b[j] = b4.x; b[j + 1] = b4.y; b[j + 2] = b4.z; b[j + 3] = b4.w;
            }
            #pragma unroll
            for (int i = 0; i < 4; i++)
                #pragma unroll
                for (int j = 0; j < TN; j++)
                    acc[i][j] = fmaf(a[i], b[j], acc[i][j]);
        }
        __syncthreads();
    }

    #pragma unroll
    for (int i = 0; i < 4; i++) {
        int r = bm + ty * 4 + i;
        if (r < M) {
            #pragma unroll
            for (int j = 0; j < TN; j += 4) {
                float4 v = make_float4(acc[i][j], acc[i][j+1], acc[i][j+2], acc[i][j+3]);
                *(float4*)(C + (size_t)r * NO + tx * TN + j) = v;
            }
        }
    }
}

// ---------------- gather-based aggregation: one warp per destination node ----------------
// out[c,:] = act( sum_{e:col=c} norm_e * hin[src_e,:] + dinv[c]^2 * hin[c,:] + bias )
// LAYER 0 (F=128, sigmoid): hin = g_xw4, hout = g_h4
// LAYER 1 (F=64,  tanh):    hin = g_hw4, hout = d_out (param)
template<int F, int LAYER>
__global__ __launch_bounds__(256) void k_agg(const float* __restrict__ bias,
                                             float* __restrict__ out_param) {
    int gw   = (blockIdx.x * blockDim.x + threadIdx.x) >> 5;
    int lane = threadIdx.x & 31;
    if (gw >= N_NODES) return;
    const int c = gw;
    const int e0 = g_rowptr[c];
    const int e1 = g_rowptr[c + 1];

    if constexpr (F == 128) {
        const float4* __restrict__ hv = (const float4*)g_xw4;
        float4 acc = make_float4(0.f, 0.f, 0.f, 0.f);
        for (int p = e0; p < e1; p++) {
            int   r = g_csr_src[p];
            float w = g_csr_w[p];
            float4 v = hv[(size_t)r * 32 + lane];
            acc.x = fmaf(w, v.x, acc.x); acc.y = fmaf(w, v.y, acc.y);
            acc.z = fmaf(w, v.z, acc.z); acc.w = fmaf(w, v.w, acc.w);
        }
        float di = g_dinv[c];
        float sw = di * di;
        float4 v = hv[(size_t)c * 32 + lane];
        acc.x = fmaf(sw, v.x, acc.x); acc.y = fmaf(sw, v.y, acc.y);
        acc.z = fmaf(sw, v.z, acc.z); acc.w = fmaf(sw, v.w, acc.w);
        float4 bb = ((const float4*)bias)[lane];
        acc.x += bb.x; acc.y += bb.y; acc.z += bb.z; acc.w += bb.w;
        acc.x = 1.f / (1.f + __expf(-acc.x));
        acc.y = 1.f / (1.f + __expf(-acc.y));
        acc.z = 1.f / (1.f + __expf(-acc.z));
        acc.w = 1.f / (1.f + __expf(-acc.w));
        g_h4[(size_t)c * 32 + lane] = acc;
    } else {  // F == 64
        const float2* __restrict__ hv = (const float2*)g_hw4;
        float2 acc = make_float2(0.f, 0.f);
        for (int p = e0; p < e1; p++) {
            int   r = g_csr_src[p];
            float w = g_csr_w[p];
            float2 v = hv[(size_t)r * 32 + lane];
            acc.x = fmaf(w, v.x, acc.x);
            acc.y = fmaf(w, v.y, acc.y);
        }
        float di = g_dinv[c];
        float sw = di * di;
        float2 v = hv[(size_t)c * 32 + lane];
        acc.x = fmaf(sw, v.x, acc.x);
        acc.y = fmaf(sw, v.y, acc.y);
        float2 bb = ((const float2*)bias)[lane];
        acc.x += bb.x; acc.y += bb.y;
        acc.x = tanhf(acc.x);
        acc.y = tanhf(acc.y);
        ((float2*)out_param)[(size_t)c * 32 + lane] = acc;
    }
}

// ---------------- launch ----------------
extern "C" void kernel_launch(void* const* d_in, const int* in_sizes, int n_in,
                              void* d_out, int out_size) {
    const float* x  = (const float*)d_in[0];
    const int*   ei = (const int*)d_in[1];     // int32 edge_index (2, E) row-major
    const float* ew = (const float*)d_in[2];
    const float* W1 = (const float*)d_in[3];
    const float* b1 = (const float*)d_in[4];
    const float* W2 = (const float*)d_in[5];
    const float* b2 = (const float*)d_in[6];
    float*       out = (float*)d_out;

    const int TB = 256;
    const int nblk_nodes = (N_NODES + TB - 1) / TB;       // 196
    const int nblk_edges = (N_EDGES + TB - 1) / TB;       // 6250
    const int nblk_warp  = (N_NODES * 32 + TB - 1) / TB;  // 6250

    // ---- normalization + CSR build (recomputed every call; deterministic work) ----
    k_init <<<nblk_nodes, TB>>>();
    k_deg  <<<nblk_edges, TB>>>(ei, ew);
    k_dinv <<<nblk_nodes, TB>>>();
    k_scan1<<<NBLK_SCAN, SCAN_B>>>();
    k_scan2<<<1, 64>>>();
    k_scan3<<<NBLK_SCAN, SCAN_B>>>();
    k_scatter<<<nblk_edges, TB>>>(ei, ew);

    // ---- layer 1 ----
    k_gemm<N_FEAT, N_HID, 0><<<(N_NODES + 63) / 64, 256>>>(x, W1, N_NODES);
    k_agg<N_HID, 0><<<nblk_warp, TB>>>(b1, nullptr);

    // ---- layer 2 ----
    k_gemm<N_HID, N_CLASS, 1><<<(N_NODES + 63) / 64, 256>>>(nullptr, W2, N_NODES);
    k_agg<N_CLASS, 1><<<nblk_warp, TB>>>(b2, out);
}

// round 4
// speedup vs baseline: 1.2268x; 1.2268x over previous
#include <cuda_runtime.h>
#include <cstdint>

#define N_NODES 50000
#define N_EDGES 1600000
#define N_FEAT  256
#define N_HID   128
#define N_CLASS 64

#define SCAN_B 1024
#define NBLK_SCAN ((N_NODES + SCAN_B - 1) / SCAN_B)   // 49

// ---------------- device scratch (static, no allocations) ----------------
__device__ float g_deg[N_NODES];
__device__ float g_dinv[N_NODES];
__device__ int   g_cnt[N_NODES];
__device__ int   g_scan_tmp[N_NODES];
__device__ int   g_partials[64];
__device__ int   g_rowptr[N_NODES + 1];
__device__ int   g_loc[N_EDGES];            // per-edge local slot within its dest segment
__device__ int2  g_csr[N_EDGES];            // packed (src, __float_as_int(norm))
// float4-typed for guaranteed 16B alignment of vector accesses
__device__ float4 g_xw4[(size_t)N_NODES * (N_HID / 4)];    // x @ W1     [N,128]
__device__ float4 g_h4 [(size_t)N_NODES * (N_HID / 4)];    // sigmoid(.) [N,128]
__device__ float4 g_hw4[(size_t)N_NODES * (N_CLASS / 4)];  // h @ W2     [N,64]

// ---------------- prep kernels ----------------
__global__ void k_init() {
    int i = blockIdx.x * blockDim.x + threadIdx.x;
    if (i < N_NODES) { g_deg[i] = 1.0f; g_cnt[i] = 0; }   // self-loop weight 1
}

__global__ void k_deg(const int* __restrict__ ei, const float* __restrict__ ew) {
    int e = blockIdx.x * blockDim.x + threadIdx.x;
    if (e < N_EDGES) {
        int c = ei[N_EDGES + e];
        if ((unsigned)c < N_NODES) {
            atomicAdd(&g_deg[c], ew[e]);
            g_loc[e] = atomicAdd(&g_cnt[c], 1);
        }
    }
}

__global__ void k_scan1() {   // block-inclusive scan of cnt; also computes dinv
    __shared__ int s[SCAN_B];
    int i = blockIdx.x * SCAN_B + threadIdx.x;
    if (i < N_NODES) {
        float d = g_deg[i];
        g_dinv[i] = (d > 0.f) ? rsqrtf(d) : 0.f;
    }
    int v = (i < N_NODES) ? g_cnt[i] : 0;
    s[threadIdx.x] = v;
    __syncthreads();
    for (int off = 1; off < SCAN_B; off <<= 1) {
        int t = (threadIdx.x >= off) ? s[threadIdx.x - off] : 0;
        __syncthreads();
        s[threadIdx.x] += t;
        __syncthreads();
    }
    if (i < N_NODES) g_scan_tmp[i] = s[threadIdx.x];      // inclusive
    if (threadIdx.x == SCAN_B - 1) g_partials[blockIdx.x] = s[SCAN_B - 1];
}

__global__ void k_scan2() {
    __shared__ int s[64];
    int t = threadIdx.x;
    int v = (t < NBLK_SCAN) ? g_partials[t] : 0;
    s[t] = v;
    __syncthreads();
    for (int off = 1; off < 64; off <<= 1) {
        int u = (t >= off) ? s[t - off] : 0;
        __syncthreads();
        s[t] += u;
        __syncthreads();
    }
    if (t < NBLK_SCAN) g_partials[t] = s[t] - v;          // exclusive
}

__global__ void k_scan3() {
    int i = blockIdx.x * SCAN_B + threadIdx.x;
    if (i < N_NODES) {
        g_rowptr[i] = g_scan_tmp[i] - g_cnt[i] + g_partials[blockIdx.x];
    }
    if (i == 0) g_rowptr[N_NODES] = N_EDGES;
}

__global__ void k_scatter(const int* __restrict__ ei, const float* __restrict__ ew) {
    int e = blockIdx.x * blockDim.x + threadIdx.x;
    if (e < N_EDGES) {
        int r = ei[e];
        int c = ei[N_EDGES + e];
        if ((unsigned)r < N_NODES && (unsigned)c < N_NODES) {
            float nrm = g_dinv[r] * ew[e] * g_dinv[c];
            int p = g_rowptr[c] + g_loc[e];          // atomic-free placement
            g_csr[p] = make_int2(r, __float_as_int(nrm));
        }
    }
}

// ---------------- fp32 register-tiled GEMM: 128xNO block tile, TMxTN microtile ----------------
// LAYER 0: C = x(param) @ W1 -> g_xw4   (K=256, NO=128, TM=8, TN=8)
// LAYER 1: C = g_h @ W2      -> g_hw4   (K=128, NO=64,  TM=8, TN=4)
template<int K, int NO, int TM, int TN, int LAYER>
__global__ __launch_bounds__(256) void k_gemm(const float* __restrict__ Ain,
                                              const float* __restrict__ B, int M) {
    const float* __restrict__ A = (LAYER == 0) ? Ain : (const float*)g_h4;
    float* __restrict__ C = (LAYER == 0) ? (float*)g_xw4 : (float*)g_hw4;

    constexpr int BK = 16;
    constexpr int NX = NO / TN;              // 16 column groups
    constexpr int NY = 256 / NX;             // 16 row groups
    constexpr int BM = NY * TM;              // 128
    constexpr int CNT_A = BM * BK / (4 * 256);   // float4 A-loads per thread (=2)
    constexpr int CNT_B = BK * NO / (4 * 256);   // float4 B-loads per thread (2 or 1)

    __shared__ float As[BK][BM];             // A tile, transposed
    __shared__ float Bs[BK][NO];

    const int tid = threadIdx.x;
    const int bm  = blockIdx.x * BM;
    const int tx  = tid % NX;
    const int ty  = tid / NX;

    float acc[TM][TN];
    #pragma unroll
    for (int i = 0; i < TM; i++)
        #pragma unroll
        for (int j = 0; j < TN; j++) acc[i][j] = 0.f;

    for (int k0 = 0; k0 < K; k0 += BK) {
        // A tile: BM x BK floats; row-major A, BK/4 = 4 float4 per row
        #pragma unroll
        for (int i = 0; i < CNT_A; i++) {
            int t  = tid + i * 256;
            int r  = t >> 2;
            int c4 = (t & 3) << 2;
            float4 v = make_float4(0.f, 0.f, 0.f, 0.f);
            if (bm + r < M)
                v = *(const float4*)(A + (size_t)(bm + r) * K + k0 + c4);
            As[c4 + 0][r] = v.x; As[c4 + 1][r] = v.y;
            As[c4 + 2][r] = v.z; As[c4 + 3][r] = v.w;
        }
        // B tile: BK x NO floats
        #pragma unroll
        for (int i = 0; i < CNT_B; i++) {
            int t  = tid + i * 256;
            int r  = t / (NO / 4);
            int c4 = (t % (NO / 4)) << 2;
            *(float4*)&Bs[r][c4] = *(const float4*)(B + (size_t)(k0 + r) * NO + c4);
        }
        __syncthreads();

        #pragma unroll
        for (int k = 0; k < BK; k++) {
            float a[TM], b[TN];
            #pragma unroll
            for (int i = 0; i < TM; i += 4) {
                float4 a4 = *(const float4*)&As[k][ty * TM + i];
                a[i] = a4.x; a[i+1] = a4.y; a[i+2] = a4.z; a[i+3] = a4.w;
            }
            #pragma unroll
            for (int j = 0; j < TN; j += 4) {
                float4 b4 = *(const float4*)&Bs[k][tx * TN + j];
                b[j] = b4.x; b[j+1] = b4.y; b[j+2] = b4.z; b[j+3] = b4.w;
            }
            #pragma unroll
            for (int i = 0; i < TM; i++)
                #pragma unroll
                for (int j = 0; j < TN; j++)
                    acc[i][j] = fmaf(a[i], b[j], acc[i][j]);
        }
        __syncthreads();
    }

    #pragma unroll
    for (int i = 0; i < TM; i++) {
        int r = bm + ty * TM + i;
        if (r < M) {
            #pragma unroll
            for (int j = 0; j < TN; j += 4) {
                float4 v = make_float4(acc[i][j], acc[i][j+1], acc[i][j+2], acc[i][j+3]);
                *(float4*)(C + (size_t)r * NO + tx * TN + j) = v;
            }
        }
    }
}

// ---------------- gather-based aggregation: one warp per destination node ----------------
// out[c,:] = act( sum_{e:col=c} norm_e * hin[src_e,:] + dinv[c]^2 * hin[c,:] + bias )
template<int F, int LAYER>
__global__ __launch_bounds__(256) void k_agg(const float* __restrict__ bias,
                                             float* __restrict__ out_param) {
    int gw   = (blockIdx.x * blockDim.x + threadIdx.x) >> 5;
    int lane = threadIdx.x & 31;
    if (gw >= N_NODES) return;
    const int c = gw;
    const int e0 = g_rowptr[c];
    const int e1 = g_rowptr[c + 1];
    const int2* __restrict__ csr = g_csr;

    if constexpr (F == 128) {
        const float4* __restrict__ hv = (const float4*)g_xw4;
        float4 acc = make_float4(0.f, 0.f, 0.f, 0.f);
        int p = e0;
        for (; p + 4 <= e1; p += 4) {           // 4 independent gathers in flight
            int2 s0 = csr[p], s1 = csr[p+1], s2 = csr[p+2], s3 = csr[p+3];
            float4 v0 = hv[(size_t)s0.x * 32 + lane];
            float4 v1 = hv[(size_t)s1.x * 32 + lane];
            float4 v2 = hv[(size_t)s2.x * 32 + lane];
            float4 v3 = hv[(size_t)s3.x * 32 + lane];
            float w0 = __int_as_float(s0.y), w1 = __int_as_float(s1.y);
            float w2 = __int_as_float(s2.y), w3 = __int_as_float(s3.y);
            acc.x = fmaf(w0, v0.x, acc.x); acc.y = fmaf(w0, v0.y, acc.y);
            acc.z = fmaf(w0, v0.z, acc.z); acc.w = fmaf(w0, v0.w, acc.w);
            acc.x = fmaf(w1, v1.x, acc.x); acc.y = fmaf(w1, v1.y, acc.y);
            acc.z = fmaf(w1, v1.z, acc.z); acc.w = fmaf(w1, v1.w, acc.w);
            acc.x = fmaf(w2, v2.x, acc.x); acc.y = fmaf(w2, v2.y, acc.y);
            acc.z = fmaf(w2, v2.z, acc.z); acc.w = fmaf(w2, v2.w, acc.w);
            acc.x = fmaf(w3, v3.x, acc.x); acc.y = fmaf(w3, v3.y, acc.y);
            acc.z = fmaf(w3, v3.z, acc.z); acc.w = fmaf(w3, v3.w, acc.w);
        }
        for (; p < e1; p++) {
            int2 s = csr[p];
            float w = __int_as_float(s.y);
            float4 v = hv[(size_t)s.x * 32 + lane];
            acc.x = fmaf(w, v.x, acc.x); acc.y = fmaf(w, v.y, acc.y);
            acc.z = fmaf(w, v.z, acc.z); acc.w = fmaf(w, v.w, acc.w);
        }
        float di = g_dinv[c];
        float sw = di * di;
        float4 v = hv[(size_t)c * 32 + lane];
        acc.x = fmaf(sw, v.x, acc.x); acc.y = fmaf(sw, v.y, acc.y);
        acc.z = fmaf(sw, v.z, acc.z); acc.w = fmaf(sw, v.w, acc.w);
        float4 bb = ((const float4*)bias)[lane];
        acc.x += bb.x; acc.y += bb.y; acc.z += bb.z; acc.w += bb.w;
        acc.x = 1.f / (1.f + __expf(-acc.x));
        acc.y = 1.f / (1.f + __expf(-acc.y));
        acc.z = 1.f / (1.f + __expf(-acc.z));
        acc.w = 1.f / (1.f + __expf(-acc.w));
        g_h4[(size_t)c * 32 + lane] = acc;
    } else {  // F == 64
        const float2* __restrict__ hv = (const float2*)g_hw4;
        float2 acc = make_float2(0.f, 0.f);
        int p = e0;
        for (; p + 4 <= e1; p += 4) {
            int2 s0 = csr[p], s1 = csr[p+1], s2 = csr[p+2], s3 = csr[p+3];
            float2 v0 = hv[(size_t)s0.x * 32 + lane];
            float2 v1 = hv[(size_t)s1.x * 32 + lane];
            float2 v2 = hv[(size_t)s2.x * 32 + lane];
            float2 v3 = hv[(size_t)s3.x * 32 + lane];
            float w0 = __int_as_float(s0.y), w1 = __int_as_float(s1.y);
            float w2 = __int_as_float(s2.y), w3 = __int_as_float(s3.y);
            acc.x = fmaf(w0, v0.x, acc.x); acc.y = fmaf(w0, v0.y, acc.y);
            acc.x = fmaf(w1, v1.x, acc.x); acc.y = fmaf(w1, v1.y, acc.y);
            acc.x = fmaf(w2, v2.x, acc.x); acc.y = fmaf(w2, v2.y, acc.y);
            acc.x = fmaf(w3, v3.x, acc.x); acc.y = fmaf(w3, v3.y, acc.y);
        }
        for (; p < e1; p++) {
            int2 s = csr[p];
            float w = __int_as_float(s.y);
            float2 v = hv[(size_t)s.x * 32 + lane];
            acc.x = fmaf(w, v.x, acc.x);
            acc.y = fmaf(w, v.y, acc.y);
        }
        float di = g_dinv[c];
        float sw = di * di;
        float2 v = hv[(size_t)c * 32 + lane];
        acc.x = fmaf(sw, v.x, acc.x);
        acc.y = fmaf(sw, v.y, acc.y);
        float2 bb = ((const float2*)bias)[lane];
        acc.x += bb.x; acc.y += bb.y;
        acc.x = tanhf(acc.x);
        acc.y = tanhf(acc.y);
        ((float2*)out_param)[(size_t)c * 32 + lane] = acc;
    }
}

// ---------------- launch ----------------
extern "C" void kernel_launch(void* const* d_in, const int* in_sizes, int n_in,
                              void* d_out, int out_size) {
    const float* x  = (const float*)d_in[0];
    const int*   ei = (const int*)d_in[1];     // int32 edge_index (2, E) row-major
    const float* ew = (const float*)d_in[2];
    const float* W1 = (const float*)d_in[3];
    const float* b1 = (const float*)d_in[4];
    const float* W2 = (const float*)d_in[5];
    const float* b2 = (const float*)d_in[6];
    float*       out = (float*)d_out;

    const int TB = 256;
    const int nblk_nodes = (N_NODES + TB - 1) / TB;       // 196
    const int nblk_edges = (N_EDGES + TB - 1) / TB;       // 6250
    const int nblk_warp  = (N_NODES * 32 + TB - 1) / TB;  // 6250

    // ---- normalization + CSR build ----
    k_init <<<nblk_nodes, TB>>>();
    k_deg  <<<nblk_edges, TB>>>(ei, ew);
    k_scan1<<<NBLK_SCAN, SCAN_B>>>();
    k_scan2<<<1, 64>>>();
    k_scan3<<<NBLK_SCAN, SCAN_B>>>();
    k_scatter<<<nblk_edges, TB>>>(ei, ew);

    // ---- layer 1 ----
    k_gemm<N_FEAT, N_HID, 8, 8, 0><<<(N_NODES + 127) / 128, 256>>>(x, W1, N_NODES);
    k_agg<N_HID, 0><<<nblk_warp, TB>>>(b1, nullptr);

    // ---- layer 2 ----
    k_gemm<N_HID, N_CLASS, 8, 4, 1><<<(N_NODES + 127) / 128, 256>>>(nullptr, W2, N_NODES);
    k_agg<N_CLASS, 1><<<nblk_warp, TB>>>(b2, out);
}